// round 15
// baseline (speedup 1.0000x reference)
#include <cuda_runtime.h>
#include <cuda_bf16.h>
#include <cstdint>
#include <cstring>

#define DIN   4096
#define DOUT  4096
#define NROWS 8192
#define TPB   128
#define BLK_COLS 128     // 4 warps x 32 cols
#define BLK_ROWS 128     // 8 m-tiles of 16 rows
#define NSLICE 4
#define A_STRIDE 48      // bytes per A-plane row: 16 bf16 (32B) + 16B pad -> ldmatrix conflict-free
#define WB_STRIDE 36     // floats per warp-buffer row (16B-aligned rows, STS at floor)

// out[r,o] = c + sum_{k<16} x[r,k]*W[o,k]
// (tstat = |y1|/sqrt(s2/16) >= 0 > TAU, so "passed" is identically false and the
//  reference collapses to this rank-16 update plus the scalar c.)
// HMMA m16n8k16 bf16 with hi/lo K-split (err ~2^-18). This revision fixes the
// L1-wavefront bottleneck: A fragments come from ldmatrix on staged bf16 smem
// planes (8 wf/m-tile vs 32), and D is transposed through per-warp smem so
// stores are full-128B-line STG.128 (1 wf per line).

__device__ __forceinline__ void mma16816(float& d0, float& d1, float& d2, float& d3,
                                         unsigned a0, unsigned a1, unsigned a2,
                                         unsigned a3, unsigned b0, unsigned b1) {
    asm volatile(
        "mma.sync.aligned.m16n8k16.row.col.f32.bf16.bf16.f32 "
        "{%0,%1,%2,%3}, {%4,%5,%6,%7}, {%8,%9}, {%0,%1,%2,%3};"
        : "+f"(d0), "+f"(d1), "+f"(d2), "+f"(d3)
        : "r"(a0), "r"(a1), "r"(a2), "r"(a3), "r"(b0), "r"(b1));
}

__device__ __forceinline__ void ldm4(unsigned* r, unsigned saddr) {
    asm volatile("ldmatrix.sync.aligned.m8n8.x4.shared.b16 {%0,%1,%2,%3}, [%4];"
                 : "=r"(r[0]), "=r"(r[1]), "=r"(r[2]), "=r"(r[3]) : "r"(saddr));
}

__device__ __forceinline__ void split2(float2 f, unsigned& hi, unsigned& lo) {
    __nv_bfloat162 h = __floats2bfloat162_rn(f.x, f.y);   // x -> low half
    memcpy(&hi, &h, 4);
    float rx = f.x - __bfloat162float(h.x);
    float ry = f.y - __bfloat162float(h.y);
    __nv_bfloat162 l = __floats2bfloat162_rn(rx, ry);
    memcpy(&lo, &l, 4);
}

__global__ __launch_bounds__(TPB) void et_hmma2_kernel(
    const float* __restrict__ x, const float* __restrict__ W,
    float* __restrict__ out)
{
    __shared__ __align__(16) unsigned char sAhi[BLK_ROWS * A_STRIDE];  // 6KB
    __shared__ __align__(16) unsigned char sAlo[BLK_ROWS * A_STRIDE];  // 6KB
    __shared__ __align__(16) float swb[4][16 * WB_STRIDE];             // 9KB
    __shared__ float sred[TPB / 32];
    __shared__ float s_c;

    const int tid  = threadIdx.x;
    const int lane = tid & 31;
    const int wid  = tid >> 5;
    const int g    = lane >> 2;          // fragment group id (row / n)
    const int t2   = (lane & 3) * 2;     // fragment k/col base
    const int r0   = blockIdx.y * BLK_ROWS;
    const int o0w  = blockIdx.x * BLK_COLS + wid * (NSLICE * 8);

    // ---- stage A planes: x[r0..r0+127, 0:16] -> bf16 hi/lo, 48B row stride ----
    {
        const int h = tid & 3;           // 16B chunk within the row prefix
#pragma unroll
        for (int it = 0; it < 4; ++it) {
            int row = it * 32 + (tid >> 2);
            float4 v = *reinterpret_cast<const float4*>(
                           x + (size_t)(r0 + row) * DIN + 4 * h);
            unsigned h0, l0, h1, l1;
            split2(make_float2(v.x, v.y), h0, l0);
            split2(make_float2(v.z, v.w), h1, l1);
            *reinterpret_cast<uint2*>(sAhi + row * A_STRIDE + 8 * h) = make_uint2(h0, h1);
            *reinterpret_cast<uint2*>(sAlo + row * A_STRIDE + 8 * h) = make_uint2(l0, l1);
        }
    }

    // ---- c = dot(W[0,16:], x[0,16:]) (vectorized f32 + warp/block reduce) ----
    {
        const float4* x4 = reinterpret_cast<const float4*>(x);
        const float4* w4 = reinterpret_cast<const float4*>(W);
        float acc = 0.0f;
#pragma unroll
        for (int k = 0; k < 8; ++k) {
            int fidx = 4 + tid + k * TPB;          // float4 index, [4,1024)
            if (fidx < DIN / 4) {
                float4 xv = x4[fidx];
                float4 wv = w4[fidx];
                acc += xv.x * wv.x + xv.y * wv.y + xv.z * wv.z + xv.w * wv.w;
            }
        }
#pragma unroll
        for (int off = 16; off > 0; off >>= 1)
            acc += __shfl_xor_sync(0xFFFFFFFFu, acc, off);
        if (lane == 0) sred[wid] = acc;
    }

    // ---- B fragments via LDG + split (once per warp) ----
    unsigned bh[NSLICE][2], bl[NSLICE][2];
#pragma unroll
    for (int s = 0; s < NSLICE; ++s) {
        const float* wr = W + (size_t)(o0w + s * 8 + g) * DIN;      // n = g
        float2 w0 = *reinterpret_cast<const float2*>(wr + t2);      // k t2
        float2 w1 = *reinterpret_cast<const float2*>(wr + t2 + 8);  // k t2+8
        split2(w0, bh[s][0], bl[s][0]);
        split2(w1, bh[s][1], bl[s][1]);
    }

    __syncthreads();                     // A planes + sred visible
    if (tid == 0) s_c = sred[0] + sred[1] + sred[2] + sred[3];
    __syncthreads();
    const float cval = s_c;

    // ---- per-lane ldmatrix addresses (m0:r0-7 k0-7, m1:r8-15 k0-7, m2/m3: k8-15)
    const int lrow = (lane & 7) + (((lane >> 3) & 1) << 3);
    const int lcol = (lane >> 4) << 4;   // 0 or 16 bytes (k 0-7 / 8-15)
    unsigned uAhi = (unsigned)__cvta_generic_to_shared(sAhi) + lrow * A_STRIDE + lcol;
    unsigned uAlo = (unsigned)__cvta_generic_to_shared(sAlo) + lrow * A_STRIDE + lcol;

    float* wb = swb[wid];                // per-warp transpose buffer (no block sync)
    const int err = lane >> 3;           // epilogue: row-within-quad
    const int ecc = (lane & 7) * 4;      // epilogue: col (floats)

#pragma unroll
    for (int mt = 0; mt < BLK_ROWS / 16; ++mt) {
        unsigned ah[4], al[4];
        ldm4(ah, uAhi);
        ldm4(al, uAlo);
        uAhi += 16 * A_STRIDE;
        uAlo += 16 * A_STRIDE;

#pragma unroll
        for (int s = 0; s < NSLICE; ++s) {
            float d0 = cval, d1 = cval, d2 = cval, d3 = cval;
            mma16816(d0, d1, d2, d3, ah[0], ah[1], ah[2], ah[3], bh[s][0], bh[s][1]);
            mma16816(d0, d1, d2, d3, al[0], al[1], al[2], al[3], bh[s][0], bh[s][1]);
            mma16816(d0, d1, d2, d3, ah[0], ah[1], ah[2], ah[3], bl[s][0], bl[s][1]);
            // D frag -> warp buffer: (row g, col s*8+t2) / (row g+8)
            *reinterpret_cast<float2*>(&wb[g * WB_STRIDE + s * 8 + t2]) =
                make_float2(d0, d1);
            *reinterpret_cast<float2*>(&wb[(g + 8) * WB_STRIDE + s * 8 + t2]) =
                make_float2(d2, d3);
        }
        __syncwarp();

        // coalesced write-out: 4 iters x (4 rows x 128B full lines)
#pragma unroll
        for (int it = 0; it < 4; ++it) {
            int rr = it * 4 + err;
            float4 v = *reinterpret_cast<const float4*>(&wb[rr * WB_STRIDE + ecc]);
            *reinterpret_cast<float4*>(
                out + (size_t)(r0 + mt * 16 + rr) * DOUT + o0w + ecc) = v;
        }
        __syncwarp();                    // before next m-tile reuses wb
    }
}

extern "C" void kernel_launch(void* const* d_in, const int* in_sizes, int n_in,
                              void* d_out, int out_size) {
    const float* x = (const float*)d_in[0];   // (4,2048,4096) f32
    const float* W = (const float*)d_in[1];   // (4096,4096)  f32
    float* out = (float*)d_out;               // (4,2048,4096) f32

    dim3 grid(DOUT / BLK_COLS, NROWS / BLK_ROWS);   // (32, 64) = 2048 blocks
    et_hmma2_kernel<<<grid, TPB>>>(x, W, out);
}

// round 17
// speedup vs baseline: 1.6279x; 1.6279x over previous
#include <cuda_runtime.h>
#include <cuda_bf16.h>
#include <cstdint>
#include <cstring>

#define DIN   4096
#define DOUT  4096
#define NROWS 8192
#define TPB   128
#define BLK_COLS 128     // 4 warps x 32 cols
#define BLK_ROWS 128     // 8 m-tiles of 16 rows
#define NSLICE 4
#define A_STRIDE 48      // bytes/row in A planes: 32B data + 16B pad (ldmatrix conflict-free)

// out[r,o] = c + sum_{k<16} x[r,k]*W[o,k]
// (tstat = |y1|/sqrt(s2/16) >= 0 > TAU, so "passed" is identically false and the
//  reference collapses to this rank-16 update plus the scalar c.)
// HMMA m16n8k16 bf16 with hi/lo K-split (err ~2^-18). Epilogue: per-warp
// XOR-swizzled smem transpose -- STS.64/LDS.128 both provably bank-conflict-free,
// STG.128 writes full 128B lines (16 wf/warp-mtile, the minimum).

__device__ __forceinline__ void mma16816(float& d0, float& d1, float& d2, float& d3,
                                         unsigned a0, unsigned a1, unsigned a2,
                                         unsigned a3, unsigned b0, unsigned b1) {
    asm volatile(
        "mma.sync.aligned.m16n8k16.row.col.f32.bf16.bf16.f32 "
        "{%0,%1,%2,%3}, {%4,%5,%6,%7}, {%8,%9}, {%0,%1,%2,%3};"
        : "+f"(d0), "+f"(d1), "+f"(d2), "+f"(d3)
        : "r"(a0), "r"(a1), "r"(a2), "r"(a3), "r"(b0), "r"(b1));
}

__device__ __forceinline__ void ldm4(unsigned* r, unsigned saddr) {
    asm volatile("ldmatrix.sync.aligned.m8n8.x4.shared.b16 {%0,%1,%2,%3}, [%4];"
                 : "=r"(r[0]), "=r"(r[1]), "=r"(r[2]), "=r"(r[3]) : "r"(saddr));
}

__device__ __forceinline__ void split2(float2 f, unsigned& hi, unsigned& lo) {
    __nv_bfloat162 h = __floats2bfloat162_rn(f.x, f.y);   // x -> low half
    memcpy(&hi, &h, 4);
    float rx = f.x - __bfloat162float(h.x);
    float ry = f.y - __bfloat162float(h.y);
    __nv_bfloat162 l = __floats2bfloat162_rn(rx, ry);
    memcpy(&lo, &l, 4);
}

__global__ __launch_bounds__(TPB) void et_hmma3_kernel(
    const float* __restrict__ x, const float* __restrict__ W,
    float* __restrict__ out)
{
    __shared__ __align__(16) unsigned char sAhi[BLK_ROWS * A_STRIDE];  // 6KB
    __shared__ __align__(16) unsigned char sAlo[BLK_ROWS * A_STRIDE];  // 6KB
    __shared__ __align__(16) float swb[4][16 * 32];                    // 8KB
    __shared__ float sred[TPB / 32];
    __shared__ float s_c;

    const int tid  = threadIdx.x;
    const int lane = tid & 31;
    const int wid  = tid >> 5;
    const int g    = lane >> 2;          // fragment row group 0..7
    const int q    = lane & 3;           // fragment col quad
    const int r0   = blockIdx.y * BLK_ROWS;
    const int o0w  = blockIdx.x * BLK_COLS + wid * (NSLICE * 8);

    // ---- stage A planes: x[r0..r0+127, 0:16] -> bf16 hi/lo, 48B row stride ----
    {
        const int h = tid & 3;           // 16B chunk within the row prefix
#pragma unroll
        for (int it = 0; it < 4; ++it) {
            int row = it * 32 + (tid >> 2);
            float4 v = *reinterpret_cast<const float4*>(
                           x + (size_t)(r0 + row) * DIN + 4 * h);
            unsigned h0, l0, h1, l1;
            split2(make_float2(v.x, v.y), h0, l0);
            split2(make_float2(v.z, v.w), h1, l1);
            *reinterpret_cast<uint2*>(sAhi + row * A_STRIDE + 8 * h) = make_uint2(h0, h1);
            *reinterpret_cast<uint2*>(sAlo + row * A_STRIDE + 8 * h) = make_uint2(l0, l1);
        }
    }

    // ---- c = dot(W[0,16:], x[0,16:]) (vectorized f32 + warp/block reduce) ----
    {
        const float4* x4 = reinterpret_cast<const float4*>(x);
        const float4* w4 = reinterpret_cast<const float4*>(W);
        float acc = 0.0f;
#pragma unroll
        for (int k = 0; k < 8; ++k) {
            int fidx = 4 + tid + k * TPB;          // float4 index, [4,1024)
            if (fidx < DIN / 4) {
                float4 xv = x4[fidx];
                float4 wv = w4[fidx];
                acc += xv.x * wv.x + xv.y * wv.y + xv.z * wv.z + xv.w * wv.w;
            }
        }
#pragma unroll
        for (int off = 16; off > 0; off >>= 1)
            acc += __shfl_xor_sync(0xFFFFFFFFu, acc, off);
        if (lane == 0) sred[wid] = acc;
    }

    // ---- B fragments via LDG + split (once per warp) ----
    unsigned bh[NSLICE][2], bl[NSLICE][2];
#pragma unroll
    for (int s = 0; s < NSLICE; ++s) {
        const float* wr = W + (size_t)(o0w + s * 8 + g) * DIN;        // n = g
        float2 w0 = *reinterpret_cast<const float2*>(wr + 2 * q);     // k 2q
        float2 w1 = *reinterpret_cast<const float2*>(wr + 2 * q + 8); // k 2q+8
        split2(w0, bh[s][0], bl[s][0]);
        split2(w1, bh[s][1], bl[s][1]);
    }

    __syncthreads();                     // A planes + sred visible
    if (tid == 0) s_c = sred[0] + sred[1] + sred[2] + sred[3];
    __syncthreads();
    const float cval = s_c;

    // ---- per-lane ldmatrix addresses ----
    const int lrow = (lane & 7) + (((lane >> 3) & 1) << 3);
    const int lcol = (lane >> 4) << 4;   // 0 or 16 bytes (k 0-7 / 8-15)
    unsigned uAhi = (unsigned)__cvta_generic_to_shared(sAhi) + lrow * A_STRIDE + lcol;
    unsigned uAlo = (unsigned)__cvta_generic_to_shared(sAlo) + lrow * A_STRIDE + lcol;

    float* wb = swb[wid];                // per-warp swizzled transpose buffer
    const int sts_base_lo = g * 32 + 2 * q;          // + 8*(s^(g&3))
    const int sts_base_hi = (g + 8) * 32 + 2 * q;
    const int gx3 = g & 3;

    // epilogue mapping: lane -> (row-within-4, float4 index)
    const int e_r = lane >> 3;           // 0..3
    const int e_f = lane & 7;            // 0..7
    // swizzled read offset within a row: 8*((f>>1)^(rr&3)) + 4*(f&1)

#pragma unroll
    for (int mt = 0; mt < BLK_ROWS / 16; ++mt) {
        unsigned ah[4], al[4];
        ldm4(ah, uAhi);
        ldm4(al, uAlo);
        uAhi += 16 * A_STRIDE;
        uAlo += 16 * A_STRIDE;

#pragma unroll
        for (int s = 0; s < NSLICE; ++s) {
            float d0 = cval, d1 = cval, d2 = cval, d3 = cval;
            mma16816(d0, d1, d2, d3, ah[0], ah[1], ah[2], ah[3], bh[s][0], bh[s][1]);
            mma16816(d0, d1, d2, d3, al[0], al[1], al[2], al[3], bh[s][0], bh[s][1]);
            mma16816(d0, d1, d2, d3, ah[0], ah[1], ah[2], ah[3], bl[s][0], bl[s][1]);
            // swizzled STS.64: slot xor keeps all 16 bankpairs distinct per phase
            const int sw = 8 * (s ^ gx3);
            *reinterpret_cast<float2*>(&wb[sts_base_lo + sw]) = make_float2(d0, d1);
            *reinterpret_cast<float2*>(&wb[sts_base_hi + sw]) = make_float2(d2, d3);
        }
        __syncwarp();

        // coalesced write-out: 4 insts x 4 rows x full 128B lines
#pragma unroll
        for (int it = 0; it < 4; ++it) {
            int rr = it * 4 + e_r;
            float4 v = *reinterpret_cast<const float4*>(
                &wb[rr * 32 + 8 * ((e_f >> 1) ^ (rr & 3)) + 4 * (e_f & 1)]);
            *reinterpret_cast<float4*>(
                out + (size_t)(r0 + mt * 16 + rr) * DOUT + o0w + 4 * e_f) = v;
        }
        __syncwarp();                    // before next m-tile reuses wb
    }
}

extern "C" void kernel_launch(void* const* d_in, const int* in_sizes, int n_in,
                              void* d_out, int out_size) {
    const float* x = (const float*)d_in[0];   // (4,2048,4096) f32
    const float* W = (const float*)d_in[1];   // (4096,4096)  f32
    float* out = (float*)d_out;               // (4,2048,4096) f32

    dim3 grid(DOUT / BLK_COLS, NROWS / BLK_ROWS);   // (32, 64) = 2048 blocks
    et_hmma3_kernel<<<grid, TPB>>>(x, W, out);
}